// round 8
// baseline (speedup 1.0000x reference)
#include <cuda_runtime.h>
#include <cuda_bf16.h>
#include <cstdint>
#include <math.h>

// Problem constants
#define NG      64          // num graphs
#define NN      512         // nodes per graph
#define GN      32768       // NG*NN
#define D_IN    128
#define E       256
#define NL      4
#define DFF     2048
#define NE_EDGE 524288
#define KSEL    128
#define NH      8
#define HD      32

#define OFF_SAMP (NE_EDGE)
#define OFF_PF   (NE_EDGE + NG * KSEL)

// ---------------- scratch (static device globals; no cudaMalloc allowed) ---
__device__ float g_h[(size_t)GN * E];       // 32 MB  hidden state
__device__ float g_qkv[(size_t)GN * 3 * E]; // 96 MB
__device__ float g_attn[(size_t)GN * E];    // 32 MB  attn output / ff2 output
__device__ float g_ff[(size_t)GN * DFF];    // 256 MB out-proj result then ff1 act
__device__ float g_probs[GN];
__device__ float g_pf[GN];

// ---------------- tf32 helpers ---------------------------------------------
__device__ __forceinline__ float tf32_rna(float x) {
    uint32_t r;
    asm("cvt.rna.tf32.f32 %0, %1;" : "=r"(r) : "f"(x));
    return __uint_as_float(r);
}

// mma.sync m16n8k8 tf32 (baseline sm_80+ PTX — works on plain sm_103 target)
__device__ __forceinline__ void mma_tf32(float* d, const uint32_t* a, const uint32_t* b) {
    asm volatile(
        "mma.sync.aligned.m16n8k8.row.col.f32.tf32.tf32.f32 "
        "{%0,%1,%2,%3}, {%4,%5,%6,%7}, {%8,%9}, {%0,%1,%2,%3};"
        : "+f"(d[0]), "+f"(d[1]), "+f"(d[2]), "+f"(d[3])
        : "r"(a[0]), "r"(a[1]), "r"(a[2]), "r"(a[3]), "r"(b[0]), "r"(b[1]));
}

// ---------------- tf32x3 tensor-core GEMM, double-buffered pipeline --------
// C[M,N] = A[M,K] @ B[N,K]^T + bias, optional relu.
// Block tile 128x64, BK=16, 2 smem stages, 256 threads = 8 warps (4x2),
// warp tile 32x32. A/B split to hi/lo tf32 at smem-store time; 3 mma per
// fragment pair => ~fp32 accuracy. One __syncthreads per k-chunk; LDGs for
// chunk c+1 issue before mma work on chunk c.
#define BM   128
#define BN   64
#define BK   16
#define PAD_ROW 20                       // floats per smem row (16 + 4 pad)
#define ST_A_HI 0
#define ST_A_LO (BM * PAD_ROW)           // 2560
#define ST_B_HI (2 * BM * PAD_ROW)       // 5120
#define ST_B_LO (2 * BM * PAD_ROW + BN * PAD_ROW)
#define STAGE_F (2 * BM * PAD_ROW + 2 * BN * PAD_ROW)   // 7680 floats
#define GEMM_SMEM (2 * STAGE_F * 4)      // 61440 B

__global__ void __launch_bounds__(256, 2)
gemm_mma(const float* __restrict__ A, const float* __restrict__ B,
         const float* __restrict__ bias, float* __restrict__ C,
         int K, int N, int relu)
{
    extern __shared__ float sm[];

    const int tid  = threadIdx.x;
    const int warp = tid >> 5;
    const int lane = tid & 31;
    const int wm   = warp >> 1;          // 0..3  (m direction, 32 rows each)
    const int wn   = warp & 1;           // 0..1  (n direction, 32 cols each)
    const int gid  = lane >> 2;          // 0..7
    const int qid  = lane & 3;           // 0..3
    const int m0   = blockIdx.y * BM;
    const int n0   = blockIdx.x * BN;

    // per-chunk load indices: A 2 float4/thread, B 1 float4/thread
    const int ar0 = tid >> 2;            // 0..63   (rows 0..63 for i=0)
    const int ac4 = (tid & 3) * 4;       // col 0,4,8,12
    const int br  = tid >> 2;            // 0..63
    const int NC  = K >> 4;

    float acc[2][4][4];
#pragma unroll
    for (int i = 0; i < 2; i++)
#pragma unroll
        for (int j = 0; j < 4; j++)
#pragma unroll
            for (int t = 0; t < 4; t++) acc[i][j][t] = 0.f;

    float4 av[2], bv;

    // ---- prologue: load + split chunk 0 into stage 0 ----
    {
        const float* Ab = A + (size_t)m0 * K;
        const float* Bb = B + (size_t)n0 * K;
        av[0] = *(const float4*)(Ab + (size_t)ar0 * K + ac4);
        av[1] = *(const float4*)(Ab + (size_t)(ar0 + 64) * K + ac4);
        bv    = *(const float4*)(Bb + (size_t)br * K + ac4);

        float* st = sm;
#pragma unroll
        for (int i = 0; i < 2; i++) {
            int r = ar0 + 64 * i;
            float4 v = av[i], h, l;
            h.x = tf32_rna(v.x); l.x = v.x - h.x;
            h.y = tf32_rna(v.y); l.y = v.y - h.y;
            h.z = tf32_rna(v.z); l.z = v.z - h.z;
            h.w = tf32_rna(v.w); l.w = v.w - h.w;
            *(float4*)&st[ST_A_HI + r * PAD_ROW + ac4] = h;
            *(float4*)&st[ST_A_LO + r * PAD_ROW + ac4] = l;
        }
        {
            float4 v = bv, h, l;
            h.x = tf32_rna(v.x); l.x = v.x - h.x;
            h.y = tf32_rna(v.y); l.y = v.y - h.y;
            h.z = tf32_rna(v.z); l.z = v.z - h.z;
            h.w = tf32_rna(v.w); l.w = v.w - h.w;
            *(float4*)&st[ST_B_HI + br * PAD_ROW + ac4] = h;
            *(float4*)&st[ST_B_LO + br * PAD_ROW + ac4] = l;
        }
    }
    __syncthreads();

    for (int c = 0; c < NC; c++) {
        // ---- issue global loads for chunk c+1 (latency overlaps mma) ----
        const bool more = (c + 1 < NC);
        if (more) {
            const int k1 = (c + 1) * BK;
            const float* Ab = A + (size_t)m0 * K + k1;
            const float* Bb = B + (size_t)n0 * K + k1;
            av[0] = *(const float4*)(Ab + (size_t)ar0 * K + ac4);
            av[1] = *(const float4*)(Ab + (size_t)(ar0 + 64) * K + ac4);
            bv    = *(const float4*)(Bb + (size_t)br * K + ac4);
        }

        // ---- compute on stage c&1 ----
        const float* st = sm + (c & 1) * STAGE_F;
        const float* As_hi = st + ST_A_HI;
        const float* As_lo = st + ST_A_LO;
        const float* Bs_hi = st + ST_B_HI;
        const float* Bs_lo = st + ST_B_LO;

#pragma unroll
        for (int kk = 0; kk < 2; kk++) {
            const int kb = kk * 8;
            uint32_t a_hi[2][4], a_lo[2][4];
#pragma unroll
            for (int tm = 0; tm < 2; tm++) {
                int r = wm * 32 + tm * 16 + gid;
                a_hi[tm][0] = __float_as_uint(As_hi[r * PAD_ROW + kb + qid]);
                a_hi[tm][1] = __float_as_uint(As_hi[(r + 8) * PAD_ROW + kb + qid]);
                a_hi[tm][2] = __float_as_uint(As_hi[r * PAD_ROW + kb + qid + 4]);
                a_hi[tm][3] = __float_as_uint(As_hi[(r + 8) * PAD_ROW + kb + qid + 4]);
                a_lo[tm][0] = __float_as_uint(As_lo[r * PAD_ROW + kb + qid]);
                a_lo[tm][1] = __float_as_uint(As_lo[(r + 8) * PAD_ROW + kb + qid]);
                a_lo[tm][2] = __float_as_uint(As_lo[r * PAD_ROW + kb + qid + 4]);
                a_lo[tm][3] = __float_as_uint(As_lo[(r + 8) * PAD_ROW + kb + qid + 4]);
            }
            uint32_t b_hi[4][2], b_lo[4][2];
#pragma unroll
            for (int tn = 0; tn < 4; tn++) {
                int cc = wn * 32 + tn * 8 + gid;
                b_hi[tn][0] = __float_as_uint(Bs_hi[cc * PAD_ROW + kb + qid]);
                b_hi[tn][1] = __float_as_uint(Bs_hi[cc * PAD_ROW + kb + qid + 4]);
                b_lo[tn][0] = __float_as_uint(Bs_lo[cc * PAD_ROW + kb + qid]);
                b_lo[tn][1] = __float_as_uint(Bs_lo[cc * PAD_ROW + kb + qid + 4]);
            }
#pragma unroll
            for (int tm = 0; tm < 2; tm++)
#pragma unroll
                for (int tn = 0; tn < 4; tn++) {
                    mma_tf32(acc[tm][tn], a_hi[tm], b_hi[tn]);
                    mma_tf32(acc[tm][tn], a_hi[tm], b_lo[tn]);
                    mma_tf32(acc[tm][tn], a_lo[tm], b_hi[tn]);
                }
        }

        // ---- split + store chunk c+1 into the other stage ----
        if (more) {
            float* stn = sm + ((c + 1) & 1) * STAGE_F;
#pragma unroll
            for (int i = 0; i < 2; i++) {
                int r = ar0 + 64 * i;
                float4 v = av[i], h, l;
                h.x = tf32_rna(v.x); l.x = v.x - h.x;
                h.y = tf32_rna(v.y); l.y = v.y - h.y;
                h.z = tf32_rna(v.z); l.z = v.z - h.z;
                h.w = tf32_rna(v.w); l.w = v.w - h.w;
                *(float4*)&stn[ST_A_HI + r * PAD_ROW + ac4] = h;
                *(float4*)&stn[ST_A_LO + r * PAD_ROW + ac4] = l;
            }
            {
                float4 v = bv, h, l;
                h.x = tf32_rna(v.x); l.x = v.x - h.x;
                h.y = tf32_rna(v.y); l.y = v.y - h.y;
                h.z = tf32_rna(v.z); l.z = v.z - h.z;
                h.w = tf32_rna(v.w); l.w = v.w - h.w;
                *(float4*)&stn[ST_B_HI + br * PAD_ROW + ac4] = h;
                *(float4*)&stn[ST_B_LO + br * PAD_ROW + ac4] = l;
            }
        }
        __syncthreads();
    }

    // ---- epilogue: bias (+relu), write fp32 ----
#pragma unroll
    for (int tm = 0; tm < 2; tm++) {
#pragma unroll
        for (int tn = 0; tn < 4; tn++) {
            const float* d = acc[tm][tn];
            int row = m0 + wm * 32 + tm * 16 + gid;
            int col = n0 + wn * 32 + tn * 8 + 2 * qid;
            float bx = bias[col], by = bias[col + 1];
            float2 v0 = make_float2(d[0] + bx, d[1] + by);
            float2 v1 = make_float2(d[2] + bx, d[3] + by);
            if (relu) {
                v0.x = fmaxf(v0.x, 0.f); v0.y = fmaxf(v0.y, 0.f);
                v1.x = fmaxf(v1.x, 0.f); v1.y = fmaxf(v1.y, 0.f);
            }
            *(float2*)(C + (size_t)row * N + col) = v0;
            *(float2*)(C + (size_t)(row + 8) * N + col) = v1;
        }
    }
}

// ---------------- flash-style attention (fp32, proven version) -------------
__global__ void attn_kernel(const float* __restrict__ qkv, float* __restrict__ out)
{
    __shared__ float Ks[64][32];
    __shared__ float Vs[64][32];

    const int g  = blockIdx.x >> 3;
    const int h  = blockIdx.x & 7;
    const int tid = threadIdx.x;
    const int qi = blockIdx.y * 128 + tid;       // 0..511
    const int hc = h * HD;
    const float* base = qkv + (size_t)g * NN * (3 * E);

    float q[HD];
#pragma unroll
    for (int d = 0; d < HD; d++) q[d] = base[(size_t)qi * (3 * E) + hc + d];

    float acc[HD];
#pragma unroll
    for (int d = 0; d < HD; d++) acc[d] = 0.f;
    float mval = -1e30f, l = 0.f;
    const float scale = 0.17677669529663687f;    // 1/sqrt(32)

#pragma unroll 1
    for (int kt = 0; kt < NN; kt += 64) {
        const int row  = tid >> 1;
        const int half = (tid & 1) * 16;
        const float* kp = base + (size_t)(kt + row) * (3 * E) + E + hc + half;
        const float* vp = base + (size_t)(kt + row) * (3 * E) + 2 * E + hc + half;
#pragma unroll
        for (int c = 0; c < 16; c += 4) {
            *(float4*)&Ks[row][half + c] = *(const float4*)(kp + c);
            *(float4*)&Vs[row][half + c] = *(const float4*)(vp + c);
        }
        __syncthreads();

#pragma unroll 1
        for (int jc = 0; jc < 64; jc += 16) {
            float s[16];
            float cmax = -1e30f;
#pragma unroll
            for (int j = 0; j < 16; j++) {
                float sv = 0.f;
#pragma unroll
                for (int d = 0; d < HD; d++) sv = fmaf(q[d], Ks[jc + j][d], sv);
                sv *= scale;
                s[j] = sv;
                cmax = fmaxf(cmax, sv);
            }
            float mnew = fmaxf(mval, cmax);
            float corr = __expf(mval - mnew);
            l *= corr;
#pragma unroll
            for (int d = 0; d < HD; d++) acc[d] *= corr;
#pragma unroll
            for (int j = 0; j < 16; j++) {
                float p = __expf(s[j] - mnew);
                l += p;
#pragma unroll
                for (int d = 0; d < HD; d++)
                    acc[d] = fmaf(p, Vs[jc + j][d], acc[d]);
            }
            mval = mnew;
        }
        __syncthreads();
    }

    float inv = 1.f / l;
    float* op = out + (size_t)(g * NN + qi) * E + hc;
#pragma unroll
    for (int d = 0; d < HD; d++) op[d] = acc[d] * inv;
}

// ---------------- fused residual + LayerNorm (two-pass, fp32) --------------
__global__ void ln_kernel(float* __restrict__ h, const float* __restrict__ add,
                          const float* __restrict__ w, const float* __restrict__ b)
{
    __shared__ float red[256];
    const int r = blockIdx.x;
    const int t = threadIdx.x;
    const size_t off = (size_t)r * E + t;
    float x = h[off] + add[off];

    red[t] = x;
    __syncthreads();
#pragma unroll
    for (int s = 128; s > 0; s >>= 1) {
        if (t < s) red[t] += red[t + s];
        __syncthreads();
    }
    float mu = red[0] * (1.f / E);
    __syncthreads();

    float d = x - mu;
    red[t] = d * d;
    __syncthreads();
#pragma unroll
    for (int s = 128; s > 0; s >>= 1) {
        if (t < s) red[t] += red[t + s];
        __syncthreads();
    }
    float var = red[0] * (1.f / E);
    float y = d * rsqrtf(var + 1e-5f) * w[t] + b[t];
    h[off] = y;
}

// ---------------- score + sigmoid (warp per row) ---------------------------
__global__ void score_kernel(const float* __restrict__ h, const float* __restrict__ sw,
                             const float* __restrict__ sb, float* __restrict__ probs)
{
    const int warp = (blockIdx.x * blockDim.x + threadIdx.x) >> 5;
    const int lane = threadIdx.x & 31;
    if (warp >= GN) return;
    const float* hp = h + (size_t)warp * E;
    float s = 0.f;
#pragma unroll
    for (int k = 0; k < 8; k++) s = fmaf(hp[lane + k * 32], sw[lane + k * 32], s);
#pragma unroll
    for (int o = 16; o; o >>= 1) s += __shfl_xor_sync(0xffffffff, s, o);
    if (lane == 0) {
        s += sb[0];
        probs[warp] = 1.f / (1.f + expf(-s));
    }
}

// ---------------- per-graph top-k (k=128 of n=512) -------------------------
__global__ void topk_kernel(const float* __restrict__ probs,
                            float* __restrict__ out, float* __restrict__ pf_buf)
{
    __shared__ unsigned long long keys[NN];
    __shared__ int sidx[KSEL];
    __shared__ int flags[NN];

    const int g = blockIdx.x;
    const int t = threadIdx.x;
    const float p = probs[g * NN + t];

    unsigned int fb = __float_as_uint(p);
    keys[t] = ((unsigned long long)fb << 32) | (unsigned)(NN - 1 - t);
    __syncthreads();

    for (int k = 2; k <= NN; k <<= 1) {
        for (int j = k >> 1; j > 0; j >>= 1) {
            int ixj = t ^ j;
            if (ixj > t) {
                unsigned long long a = keys[t], b = keys[ixj];
                bool up = ((t & k) == 0);
                if (up ? (a < b) : (a > b)) { keys[t] = b; keys[ixj] = a; }
            }
            __syncthreads();
        }
    }

    if (t < KSEL) sidx[t] = NN - 1 - (int)(unsigned)(keys[t] & 0xFFFFFFFFu);
    __syncthreads();

    for (int k = 2; k <= KSEL; k <<= 1) {
        for (int j = k >> 1; j > 0; j >>= 1) {
            int ixj = t ^ j;
            if (t < KSEL && ixj > t && ixj < KSEL) {
                int a = sidx[t], b = sidx[ixj];
                bool up = ((t & k) == 0);
                if (up ? (a > b) : (a < b)) { sidx[t] = b; sidx[ixj] = a; }
            }
            __syncthreads();
        }
    }

    flags[t] = 0;
    __syncthreads();
    if (t < KSEL) flags[sidx[t]] = 1;
    __syncthreads();

    if (t < KSEL)
        out[OFF_SAMP + g * KSEL + t] = (float)(g * NN + sidx[t]);

    float mask = (float)flags[t];
    float ind  = (mask - p) + p;
    float pf   = p * ind;
    pf_buf[g * NN + t] = pf;
    out[OFF_PF + g * NN + t] = pf;
}

// ---------------- edge weights ---------------------------------------------
__global__ void ew_kernel(const int* __restrict__ ei, const float* __restrict__ w,
                          const float* __restrict__ pf, float* __restrict__ out)
{
    int e = blockIdx.x * blockDim.x + threadIdx.x;
    if (e < NE_EDGE) {
        int s = ei[e];
        int d = ei[NE_EDGE + e];
        out[e] = w[e] * pf[s] * pf[d];
    }
}

// ---------------------------------------------------------------------------
extern "C" void kernel_launch(void* const* d_in, const int* in_sizes, int n_in,
                              void* d_out, int out_size)
{
    const float* x      = (const float*)d_in[0];
    const int*   ei     = (const int*)  d_in[1];
    const float* ew     = (const float*)d_in[2];
    const float* emb_w  = (const float*)d_in[3];
    const float* emb_b  = (const float*)d_in[4];
    const float* qkv_w  = (const float*)d_in[5];
    const float* qkv_b  = (const float*)d_in[6];
    const float* out_w  = (const float*)d_in[7];
    const float* out_b  = (const float*)d_in[8];
    const float* ln1_w  = (const float*)d_in[9];
    const float* ln1_b  = (const float*)d_in[10];
    const float* ln2_w  = (const float*)d_in[11];
    const float* ln2_b  = (const float*)d_in[12];
    const float* ff1_w  = (const float*)d_in[13];
    const float* ff1_b  = (const float*)d_in[14];
    const float* ff2_w  = (const float*)d_in[15];
    const float* ff2_b  = (const float*)d_in[16];
    const float* sc_w   = (const float*)d_in[17];
    const float* sc_b   = (const float*)d_in[18];
    float* out = (float*)d_out;

    float *h, *qkvb, *attn, *ff, *probs, *pf;
    cudaGetSymbolAddress((void**)&h,     g_h);
    cudaGetSymbolAddress((void**)&qkvb,  g_qkv);
    cudaGetSymbolAddress((void**)&attn,  g_attn);
    cudaGetSymbolAddress((void**)&ff,    g_ff);
    cudaGetSymbolAddress((void**)&probs, g_probs);
    cudaGetSymbolAddress((void**)&pf,    g_pf);

    cudaFuncSetAttribute(gemm_mma, cudaFuncAttributeMaxDynamicSharedMemorySize, GEMM_SMEM);

    // embedding: [GN,128] @ [256,128]^T -> h [GN,256]
    gemm_mma<<<dim3(E / BN, GN / BM), 256, GEMM_SMEM>>>(x, emb_w, emb_b, h, D_IN, E, 0);

    for (int l = 0; l < NL; l++) {
        const float* qw = qkv_w + (size_t)l * 3 * E * E;
        const float* qb = qkv_b + (size_t)l * 3 * E;
        const float* ow = out_w + (size_t)l * E * E;
        const float* ob = out_b + (size_t)l * E;
        const float* f1w = ff1_w + (size_t)l * DFF * E;
        const float* f1b = ff1_b + (size_t)l * DFF;
        const float* f2w = ff2_w + (size_t)l * E * DFF;
        const float* f2b = ff2_b + (size_t)l * E;

        // qkv projection -> g_qkv [GN, 768]
        gemm_mma<<<dim3(3 * E / BN, GN / BM), 256, GEMM_SMEM>>>(h, qw, qb, qkvb, E, 3 * E, 0);
        // attention -> g_attn [GN, 256]
        attn_kernel<<<dim3(NG * NH, NN / 128), 128>>>(qkvb, attn);
        // output projection -> g_ff (first GN*E floats)
        gemm_mma<<<dim3(E / BN, GN / BM), 256, GEMM_SMEM>>>(attn, ow, ob, ff, E, E, 0);
        // h = LN1(h + proj)
        ln_kernel<<<GN, E>>>(h, ff, ln1_w + (size_t)l * E, ln1_b + (size_t)l * E);
        // ff1 + relu -> g_ff [GN, 2048]
        gemm_mma<<<dim3(DFF / BN, GN / BM), 256, GEMM_SMEM>>>(h, f1w, f1b, ff, E, DFF, 1);
        // ff2 -> g_attn [GN, 256]
        gemm_mma<<<dim3(E / BN, GN / BM), 256, GEMM_SMEM>>>(ff, f2w, f2b, attn, DFF, E, 0);
        // h = LN2(h + ff)
        ln_kernel<<<GN, E>>>(h, attn, ln2_w + (size_t)l * E, ln2_b + (size_t)l * E);
    }

    // score + sigmoid
    score_kernel<<<(GN * 32 + 255) / 256, 256>>>(h, sc_w, sc_b, probs);
    // per-graph top-k, probs_f, sampled_nodes
    topk_kernel<<<NG, NN>>>(probs, out, pf);
    // edge weights
    ew_kernel<<<(NE_EDGE + 255) / 256, 256>>>(ei, ew, pf, out);
}

// round 10
// speedup vs baseline: 1.0649x; 1.0649x over previous
#include <cuda_runtime.h>
#include <cuda_bf16.h>
#include <cstdint>
#include <math.h>

// Problem constants
#define NG      64          // num graphs
#define NN      512         // nodes per graph
#define GN      32768       // NG*NN
#define D_IN    128
#define E       256
#define NL      4
#define DFF     2048
#define NE_EDGE 524288
#define KSEL    128
#define NH      8
#define HD      32

#define OFF_SAMP (NE_EDGE)
#define OFF_PF   (NE_EDGE + NG * KSEL)

// ---------------- scratch (static device globals; no cudaMalloc allowed) ---
__device__ float g_h[(size_t)GN * E];       // 32 MB  hidden state
__device__ float g_qkv[(size_t)GN * 3 * E]; // 96 MB
__device__ float g_attn[(size_t)GN * E];    // 32 MB  attn output / ff2 output
__device__ float g_ff[(size_t)GN * DFF];    // 256 MB out-proj result then ff1 act
__device__ float g_probs[GN];
__device__ float g_pf[GN];

// ---------------- tf32 helpers ---------------------------------------------
__device__ __forceinline__ float tf32_rna(float x) {
    uint32_t r;
    asm("cvt.rna.tf32.f32 %0, %1;" : "=r"(r) : "f"(x));
    return __uint_as_float(r);
}

// mma.sync m16n8k8 tf32 (baseline sm_80+ PTX — works on plain sm_103 target)
__device__ __forceinline__ void mma_tf32(float* d, const uint32_t* a, const uint32_t* b) {
    asm volatile(
        "mma.sync.aligned.m16n8k8.row.col.f32.tf32.tf32.f32 "
        "{%0,%1,%2,%3}, {%4,%5,%6,%7}, {%8,%9}, {%0,%1,%2,%3};"
        : "+f"(d[0]), "+f"(d[1]), "+f"(d[2]), "+f"(d[3])
        : "r"(a[0]), "r"(a[1]), "r"(a[2]), "r"(a[3]), "r"(b[0]), "r"(b[1]));
}

__device__ __forceinline__ void cp_async16(uint32_t smem_addr, const void* gptr) {
    asm volatile("cp.async.cg.shared.global [%0], [%1], 16;"
                 :: "r"(smem_addr), "l"(gptr));
}
__device__ __forceinline__ void cp_commit() {
    asm volatile("cp.async.commit_group;");
}

// ---------------- tf32x3 tensor-core GEMM, cp.async 2-stage ----------------
// C[M,N] = A[M,K] @ B[N,K]^T + bias, optional relu.
// Block tile 128x64, BK=32, 256 threads = 8 warps (4x2), warp tile 32x32.
// Smem holds RAW fp32 tiles (single copy). tf32 hi/lo split happens in
// registers at fragment-load time (identical numerics to storing hi/lo:
// mma truncates the lo operand the same way). cp.async overlaps the next
// chunk's global loads with the current chunk's mma work.
#define BM   128
#define BN   64
#define BK   32
#define PAD_ROW 36                         // floats per smem row (32 + 4 pad)
#define ST_A  0
#define ST_B  (BM * PAD_ROW)               // 4608
#define STAGE_F (BM * PAD_ROW + BN * PAD_ROW)   // 6912 floats
#define GEMM_SMEM (2 * STAGE_F * 4)        // 55296 B

__global__ void __launch_bounds__(256, 2)
gemm_mma(const float* __restrict__ A, const float* __restrict__ B,
         const float* __restrict__ bias, float* __restrict__ C,
         int K, int N, int relu)
{
    extern __shared__ float sm[];
    const uint32_t smb = (uint32_t)__cvta_generic_to_shared(sm);

    const int tid  = threadIdx.x;
    const int warp = tid >> 5;
    const int lane = tid & 31;
    const int wm   = warp >> 1;            // 0..3  (m direction, 32 rows each)
    const int wn   = warp & 1;             // 0..1  (n direction, 32 cols each)
    const int gid  = lane >> 2;            // 0..7
    const int qid  = lane & 3;             // 0..3
    const int m0   = blockIdx.y * BM;
    const int n0   = blockIdx.x * BN;

    // cp.async indices: A 4 float4/thread, B 2 float4/thread per chunk
    const int lr = tid >> 3;               // 0..31
    const int lc = (tid & 7) * 4;          // 0,4,...,28
    const int NC = K >> 5;

    float acc[2][4][4];
#pragma unroll
    for (int i = 0; i < 2; i++)
#pragma unroll
        for (int j = 0; j < 4; j++)
#pragma unroll
            for (int t = 0; t < 4; t++) acc[i][j][t] = 0.f;

    // stage loader: chunk c -> stage s
    auto load_stage = [&](int c, int s) {
        const float* Ab = A + (size_t)m0 * K + c * BK;
        const float* Bb = B + (size_t)n0 * K + c * BK;
        uint32_t st = smb + (uint32_t)(s * STAGE_F * 4);
#pragma unroll
        for (int i = 0; i < 4; i++) {
            int r = lr + 32 * i;           // 0..127
            cp_async16(st + (uint32_t)((ST_A + r * PAD_ROW + lc) * 4),
                       Ab + (size_t)r * K + lc);
        }
#pragma unroll
        for (int i = 0; i < 2; i++) {
            int r = lr + 32 * i;           // 0..63
            cp_async16(st + (uint32_t)((ST_B + r * PAD_ROW + lc) * 4),
                       Bb + (size_t)r * K + lc);
        }
        cp_commit();
    };

    // prologue: stages 0 and 1 in flight
    load_stage(0, 0);
    if (NC > 1) load_stage(1, 1);

    for (int c = 0; c < NC; c++) {
        // wait until chunk c's group has landed (allow c+1 outstanding)
        if (c + 1 < NC) asm volatile("cp.async.wait_group 1;" ::: "memory");
        else            asm volatile("cp.async.wait_group 0;" ::: "memory");
        __syncthreads();

        const float* st  = sm + (c & 1) * STAGE_F;
        const float* As  = st + ST_A;
        const float* Bs  = st + ST_B;

#pragma unroll
        for (int kk = 0; kk < 4; kk++) {
            const int kb = kk * 8;
            uint32_t a_hi[2][4], a_lo[2][4];
#pragma unroll
            for (int tm = 0; tm < 2; tm++) {
                int r = wm * 32 + tm * 16 + gid;
                float v0 = As[r * PAD_ROW + kb + qid];
                float v1 = As[(r + 8) * PAD_ROW + kb + qid];
                float v2 = As[r * PAD_ROW + kb + qid + 4];
                float v3 = As[(r + 8) * PAD_ROW + kb + qid + 4];
                float h0 = tf32_rna(v0), h1 = tf32_rna(v1);
                float h2 = tf32_rna(v2), h3 = tf32_rna(v3);
                a_hi[tm][0] = __float_as_uint(h0); a_lo[tm][0] = __float_as_uint(v0 - h0);
                a_hi[tm][1] = __float_as_uint(h1); a_lo[tm][1] = __float_as_uint(v1 - h1);
                a_hi[tm][2] = __float_as_uint(h2); a_lo[tm][2] = __float_as_uint(v2 - h2);
                a_hi[tm][3] = __float_as_uint(h3); a_lo[tm][3] = __float_as_uint(v3 - h3);
            }
            uint32_t b_hi[4][2], b_lo[4][2];
#pragma unroll
            for (int tn = 0; tn < 4; tn++) {
                int cc = wn * 32 + tn * 8 + gid;
                float v0 = Bs[cc * PAD_ROW + kb + qid];
                float v1 = Bs[cc * PAD_ROW + kb + qid + 4];
                float h0 = tf32_rna(v0), h1 = tf32_rna(v1);
                b_hi[tn][0] = __float_as_uint(h0); b_lo[tn][0] = __float_as_uint(v0 - h0);
                b_hi[tn][1] = __float_as_uint(h1); b_lo[tn][1] = __float_as_uint(v1 - h1);
            }
#pragma unroll
            for (int tm = 0; tm < 2; tm++)
#pragma unroll
                for (int tn = 0; tn < 4; tn++) {
                    mma_tf32(acc[tm][tn], a_hi[tm], b_hi[tn]);
                    mma_tf32(acc[tm][tn], a_hi[tm], b_lo[tn]);
                    mma_tf32(acc[tm][tn], a_lo[tm], b_hi[tn]);
                }
        }

        // refill the stage we just consumed with chunk c+2
        if (c + 2 < NC) {
            __syncthreads();               // all warps done reading stage c&1
            load_stage(c + 2, c & 1);
        }
    }

    // ---- epilogue: bias (+relu), write fp32 ----
#pragma unroll
    for (int tm = 0; tm < 2; tm++) {
#pragma unroll
        for (int tn = 0; tn < 4; tn++) {
            const float* d = acc[tm][tn];
            int row = m0 + wm * 32 + tm * 16 + gid;
            int col = n0 + wn * 32 + tn * 8 + 2 * qid;
            float bx = bias[col], by = bias[col + 1];
            float2 v0 = make_float2(d[0] + bx, d[1] + by);
            float2 v1 = make_float2(d[2] + bx, d[3] + by);
            if (relu) {
                v0.x = fmaxf(v0.x, 0.f); v0.y = fmaxf(v0.y, 0.f);
                v1.x = fmaxf(v1.x, 0.f); v1.y = fmaxf(v1.y, 0.f);
            }
            *(float2*)(C + (size_t)row * N + col) = v0;
            *(float2*)(C + (size_t)(row + 8) * N + col) = v1;
        }
    }
}

// ---------------- flash-style attention (fp32, proven version) -------------
__global__ void attn_kernel(const float* __restrict__ qkv, float* __restrict__ out)
{
    __shared__ float Ks[64][32];
    __shared__ float Vs[64][32];

    const int g  = blockIdx.x >> 3;
    const int h  = blockIdx.x & 7;
    const int tid = threadIdx.x;
    const int qi = blockIdx.y * 128 + tid;       // 0..511
    const int hc = h * HD;
    const float* base = qkv + (size_t)g * NN * (3 * E);

    float q[HD];
#pragma unroll
    for (int d = 0; d < HD; d++) q[d] = base[(size_t)qi * (3 * E) + hc + d];

    float acc[HD];
#pragma unroll
    for (int d = 0; d < HD; d++) acc[d] = 0.f;
    float mval = -1e30f, l = 0.f;
    const float scale = 0.17677669529663687f;    // 1/sqrt(32)

#pragma unroll 1
    for (int kt = 0; kt < NN; kt += 64) {
        const int row  = tid >> 1;
        const int half = (tid & 1) * 16;
        const float* kp = base + (size_t)(kt + row) * (3 * E) + E + hc + half;
        const float* vp = base + (size_t)(kt + row) * (3 * E) + 2 * E + hc + half;
#pragma unroll
        for (int c = 0; c < 16; c += 4) {
            *(float4*)&Ks[row][half + c] = *(const float4*)(kp + c);
            *(float4*)&Vs[row][half + c] = *(const float4*)(vp + c);
        }
        __syncthreads();

#pragma unroll 1
        for (int jc = 0; jc < 64; jc += 16) {
            float s[16];
            float cmax = -1e30f;
#pragma unroll
            for (int j = 0; j < 16; j++) {
                float sv = 0.f;
#pragma unroll
                for (int d = 0; d < HD; d++) sv = fmaf(q[d], Ks[jc + j][d], sv);
                sv *= scale;
                s[j] = sv;
                cmax = fmaxf(cmax, sv);
            }
            float mnew = fmaxf(mval, cmax);
            float corr = __expf(mval - mnew);
            l *= corr;
#pragma unroll
            for (int d = 0; d < HD; d++) acc[d] *= corr;
#pragma unroll
            for (int j = 0; j < 16; j++) {
                float p = __expf(s[j] - mnew);
                l += p;
#pragma unroll
                for (int d = 0; d < HD; d++)
                    acc[d] = fmaf(p, Vs[jc + j][d], acc[d]);
            }
            mval = mnew;
        }
        __syncthreads();
    }

    float inv = 1.f / l;
    float* op = out + (size_t)(g * NN + qi) * E + hc;
#pragma unroll
    for (int d = 0; d < HD; d++) op[d] = acc[d] * inv;
}

// ---------------- fused residual + LayerNorm (two-pass, fp32) --------------
__global__ void ln_kernel(float* __restrict__ h, const float* __restrict__ add,
                          const float* __restrict__ w, const float* __restrict__ b)
{
    __shared__ float red[256];
    const int r = blockIdx.x;
    const int t = threadIdx.x;
    const size_t off = (size_t)r * E + t;
    float x = h[off] + add[off];

    red[t] = x;
    __syncthreads();
#pragma unroll
    for (int s = 128; s > 0; s >>= 1) {
        if (t < s) red[t] += red[t + s];
        __syncthreads();
    }
    float mu = red[0] * (1.f / E);
    __syncthreads();

    float d = x - mu;
    red[t] = d * d;
    __syncthreads();
#pragma unroll
    for (int s = 128; s > 0; s >>= 1) {
        if (t < s) red[t] += red[t + s];
        __syncthreads();
    }
    float var = red[0] * (1.f / E);
    float y = d * rsqrtf(var + 1e-5f) * w[t] + b[t];
    h[off] = y;
}

// ---------------- score + sigmoid (warp per row) ---------------------------
__global__ void score_kernel(const float* __restrict__ h, const float* __restrict__ sw,
                             const float* __restrict__ sb, float* __restrict__ probs)
{
    const int warp = (blockIdx.x * blockDim.x + threadIdx.x) >> 5;
    const int lane = threadIdx.x & 31;
    if (warp >= GN) return;
    const float* hp = h + (size_t)warp * E;
    float s = 0.f;
#pragma unroll
    for (int k = 0; k < 8; k++) s = fmaf(hp[lane + k * 32], sw[lane + k * 32], s);
#pragma unroll
    for (int o = 16; o; o >>= 1) s += __shfl_xor_sync(0xffffffff, s, o);
    if (lane == 0) {
        s += sb[0];
        probs[warp] = 1.f / (1.f + expf(-s));
    }
}

// ---------------- per-graph top-k (k=128 of n=512) -------------------------
__global__ void topk_kernel(const float* __restrict__ probs,
                            float* __restrict__ out, float* __restrict__ pf_buf)
{
    __shared__ unsigned long long keys[NN];
    __shared__ int sidx[KSEL];
    __shared__ int flags[NN];

    const int g = blockIdx.x;
    const int t = threadIdx.x;
    const float p = probs[g * NN + t];

    unsigned int fb = __float_as_uint(p);
    keys[t] = ((unsigned long long)fb << 32) | (unsigned)(NN - 1 - t);
    __syncthreads();

    for (int k = 2; k <= NN; k <<= 1) {
        for (int j = k >> 1; j > 0; j >>= 1) {
            int ixj = t ^ j;
            if (ixj > t) {
                unsigned long long a = keys[t], b = keys[ixj];
                bool up = ((t & k) == 0);
                if (up ? (a < b) : (a > b)) { keys[t] = b; keys[ixj] = a; }
            }
            __syncthreads();
        }
    }

    if (t < KSEL) sidx[t] = NN - 1 - (int)(unsigned)(keys[t] & 0xFFFFFFFFu);
    __syncthreads();

    for (int k = 2; k <= KSEL; k <<= 1) {
        for (int j = k >> 1; j > 0; j >>= 1) {
            int ixj = t ^ j;
            if (t < KSEL && ixj > t && ixj < KSEL) {
                int a = sidx[t], b = sidx[ixj];
                bool up = ((t & k) == 0);
                if (up ? (a > b) : (a < b)) { sidx[t] = b; sidx[ixj] = a; }
            }
            __syncthreads();
        }
    }

    flags[t] = 0;
    __syncthreads();
    if (t < KSEL) flags[sidx[t]] = 1;
    __syncthreads();

    if (t < KSEL)
        out[OFF_SAMP + g * KSEL + t] = (float)(g * NN + sidx[t]);

    float mask = (float)flags[t];
    float ind  = (mask - p) + p;
    float pf   = p * ind;
    pf_buf[g * NN + t] = pf;
    out[OFF_PF + g * NN + t] = pf;
}

// ---------------- edge weights ---------------------------------------------
__global__ void ew_kernel(const int* __restrict__ ei, const float* __restrict__ w,
                          const float* __restrict__ pf, float* __restrict__ out)
{
    int e = blockIdx.x * blockDim.x + threadIdx.x;
    if (e < NE_EDGE) {
        int s = ei[e];
        int d = ei[NE_EDGE + e];
        out[e] = w[e] * pf[s] * pf[d];
    }
}

// ---------------------------------------------------------------------------
extern "C" void kernel_launch(void* const* d_in, const int* in_sizes, int n_in,
                              void* d_out, int out_size)
{
    const float* x      = (const float*)d_in[0];
    const int*   ei     = (const int*)  d_in[1];
    const float* ew     = (const float*)d_in[2];
    const float* emb_w  = (const float*)d_in[3];
    const float* emb_b  = (const float*)d_in[4];
    const float* qkv_w  = (const float*)d_in[5];
    const float* qkv_b  = (const float*)d_in[6];
    const float* out_w  = (const float*)d_in[7];
    const float* out_b  = (const float*)d_in[8];
    const float* ln1_w  = (const float*)d_in[9];
    const float* ln1_b  = (const float*)d_in[10];
    const float* ln2_w  = (const float*)d_in[11];
    const float* ln2_b  = (const float*)d_in[12];
    const float* ff1_w  = (const float*)d_in[13];
    const float* ff1_b  = (const float*)d_in[14];
    const float* ff2_w  = (const float*)d_in[15];
    const float* ff2_b  = (const float*)d_in[16];
    const float* sc_w   = (const float*)d_in[17];
    const float* sc_b   = (const float*)d_in[18];
    float* out = (float*)d_out;

    float *h, *qkvb, *attn, *ff, *probs, *pf;
    cudaGetSymbolAddress((void**)&h,     g_h);
    cudaGetSymbolAddress((void**)&qkvb,  g_qkv);
    cudaGetSymbolAddress((void**)&attn,  g_attn);
    cudaGetSymbolAddress((void**)&ff,    g_ff);
    cudaGetSymbolAddress((void**)&probs, g_probs);
    cudaGetSymbolAddress((void**)&pf,    g_pf);

    cudaFuncSetAttribute(gemm_mma, cudaFuncAttributeMaxDynamicSharedMemorySize, GEMM_SMEM);

    // embedding: [GN,128] @ [256,128]^T -> h [GN,256]
    gemm_mma<<<dim3(E / BN, GN / BM), 256, GEMM_SMEM>>>(x, emb_w, emb_b, h, D_IN, E, 0);

    for (int l = 0; l < NL; l++) {
        const float* qw = qkv_w + (size_t)l * 3 * E * E;
        const float* qb = qkv_b + (size_t)l * 3 * E;
        const float* ow = out_w + (size_t)l * E * E;
        const float* ob = out_b + (size_t)l * E;
        const float* f1w = ff1_w + (size_t)l * DFF * E;
        const float* f1b = ff1_b + (size_t)l * DFF;
        const float* f2w = ff2_w + (size_t)l * E * DFF;
        const float* f2b = ff2_b + (size_t)l * E;

        // qkv projection -> g_qkv [GN, 768]
        gemm_mma<<<dim3(3 * E / BN, GN / BM), 256, GEMM_SMEM>>>(h, qw, qb, qkvb, E, 3 * E, 0);
        // attention -> g_attn [GN, 256]
        attn_kernel<<<dim3(NG * NH, NN / 128), 128>>>(qkvb, attn);
        // output projection -> g_ff (first GN*E floats)
        gemm_mma<<<dim3(E / BN, GN / BM), 256, GEMM_SMEM>>>(attn, ow, ob, ff, E, E, 0);
        // h = LN1(h + proj)
        ln_kernel<<<GN, E>>>(h, ff, ln1_w + (size_t)l * E, ln1_b + (size_t)l * E);
        // ff1 + relu -> g_ff [GN, 2048]
        gemm_mma<<<dim3(DFF / BN, GN / BM), 256, GEMM_SMEM>>>(h, f1w, f1b, ff, E, DFF, 1);
        // ff2 -> g_attn [GN, 256]
        gemm_mma<<<dim3(E / BN, GN / BM), 256, GEMM_SMEM>>>(ff, f2w, f2b, attn, DFF, E, 0);
        // h = LN2(h + ff)
        ln_kernel<<<GN, E>>>(h, attn, ln2_w + (size_t)l * E, ln2_b + (size_t)l * E);
    }

    // score + sigmoid
    score_kernel<<<(GN * 32 + 255) / 256, 256>>>(h, sc_w, sc_b, probs);
    // per-graph top-k, probs_f, sampled_nodes
    topk_kernel<<<NG, NN>>>(probs, out, pf);
    // edge weights
    ew_kernel<<<(NE_EDGE + 255) / 256, 256>>>(ei, ew, pf, out);
}